// round 11
// baseline (speedup 1.0000x reference)
#include <cuda_runtime.h>
#include <cuda_bf16.h>

// ---------------------------------------------------------------------------
// SphericalHarmonicTransform, L=10, N=2e6 points -> 121 coefficients.
// R11 = R10 compute kernels (byte-identical) + ncu-parity dummy launches.
// Launch order per call: dummy, main, dummy, reduce  ->  ncu (-s 5 -c 1)
// captures launch #6 = the MAIN kernel for the first time.
// ---------------------------------------------------------------------------

#define NBLK 304
#define NTHR 256

__device__ float g_part[121 * NBLK];   // per-block partials, [j][block]

// ----- compile-time math -----
__host__ __device__ constexpr double cfact(int n) {
    double r = 1.0;
    for (int i = 2; i <= n; ++i) r *= (double)i;
    return r;
}
__host__ __device__ constexpr double csqrt(double x) {
    if (x <= 0.0) return 0.0;
    double g = (x > 1.0) ? x : 1.0;
    for (int i = 0; i < 200; ++i) g = 0.5 * (g + x / g);
    return g;
}
__host__ __device__ constexpr float cB(int p, int q) {
    return (float)(1.0 / (cfact(p) * cfact(q)));
}

// epilogue scales A(l,m), fully compile-time
struct ScaleTab { float v[121]; };
__host__ __device__ constexpr ScaleTab make_scales() {
    ScaleTab t{};
    for (int l = 0; l <= 10; ++l) {
        for (int M = -l; M <= l; ++M) {
            const int j  = l * l + l + M;
            const int am = (M < 0) ? -M : M;
            double s = csqrt(cfact(l + am)) * csqrt(cfact(l - am)) *
                       csqrt((2.0 * l + 1.0) /
                             (4.0 * 3.14159265358979323846264338327950288));
            if (am) s *= csqrt(2.0) * ((am & 1) ? -1.0 : 1.0);
            t.v[j] = (float)s;
        }
    }
    return t;
}
__device__ __constant__ ScaleTab SCALES = make_scales();

// ----- compile-time for -----
template <int N> struct IntC { static constexpr int value = N; };
template <int Start, int End, class F>
__device__ __forceinline__ void static_for(F&& f) {
    if constexpr (Start < End) {
        f(IntC<Start>{});
        static_for<Start + 1, End>(static_cast<F&&>(f));
    }
}

// ----- packed f32x2 helpers -----
__device__ __forceinline__ unsigned long long pack2(float lo, float hi) {
    unsigned long long r;
    asm("mov.b64 %0, {%1, %2};" : "=l"(r) : "f"(lo), "f"(hi));
    return r;
}
__device__ __forceinline__ void unpack2(unsigned long long v, float& lo, float& hi) {
    asm("mov.b64 {%0, %1}, %2;" : "=f"(lo), "=f"(hi) : "l"(v));
}
__device__ __forceinline__ unsigned long long fma2(unsigned long long a,
                                                   unsigned long long b,
                                                   unsigned long long c) {
    unsigned long long d;
    asm("fma.rn.f32x2 %0, %1, %2, %3;" : "=l"(d) : "l"(a), "l"(b), "l"(c));
    return d;
}
__device__ __forceinline__ unsigned long long mul2(unsigned long long a,
                                                   unsigned long long b) {
    unsigned long long d;
    asm("mul.rn.f32x2 %0, %1, %2;" : "=l"(d) : "l"(a), "l"(b));
    return d;
}

__host__ __device__ constexpr int aidx(int l, int m) { return l * (l - 1) / 2 + (m - 1); }

// ---------------------------------------------------------------------------
__global__ __launch_bounds__(NTHR, 1)
void sht_main_kernel(const float* __restrict__ pos, int npts) {
    unsigned long long acc2[55];   // (l,m>0): lo = +m (real), hi = -m (imag)
    float acc0[11];                // m == 0
#pragma unroll
    for (int j = 0; j < 55; ++j) acc2[j] = 0ull;
#pragma unroll
    for (int j = 0; j < 11; ++j) acc0[j] = 0.0f;

    const int stride = gridDim.x * blockDim.x;
    for (int i = blockIdx.x * blockDim.x + threadIdx.x; i < npts; i += stride) {
        const float x  = pos[3 * i + 0];
        const float y  = pos[3 * i + 1];
        const float z0 = pos[3 * i + 2];

        const float xy2 = fmaf(x, x, y * y);
        const float r2  = fmaf(z0, z0, xy2);
        const float r   = sqrtf(r2);

        // packed (w,h) chain: wh[k] = (mask*z0*r^k, r^k/k!)
        const float w0 = (r2 > 0.0f) ? z0 : 0.0f;
        unsigned long long wh[11];
        float w[11], h[11];
        unsigned long long h2[11];
        wh[0] = pack2(w0, 1.0f);
        w[0] = w0; h[0] = 1.0f;
        h2[0] = pack2(1.0f, 1.0f);
        static_for<1, 11>([&](auto sc) {
            constexpr int s = decltype(sc)::value;
            const float rs = r * (float)(1.0 / (double)s);   // FMUL-imm, rt1
            wh[s] = mul2(wh[s - 1], pack2(r, rs));           // one FMUL2
            unpack2(wh[s], w[s], h[s]);
            h2[s] = pack2(h[s], h[s]);
        });

        // packed z^p chain: z = (zr, zi), z1 = (-x/2, -y/2)
        const float ar = -0.5f * x;
        const float ai = -0.5f * y;
        const unsigned long long ar2 = pack2(ar, ar);
        const unsigned long long bi2 = pack2(-ai, ai);
        unsigned long long zP[11];
        float zr[11], zi[11];
        zP[0] = pack2(1.0f, 0.0f);
        zr[0] = 1.0f; zi[0] = 0.0f;
        static_for<1, 11>([&](auto pc) {
            constexpr int p = decltype(pc)::value;
            const unsigned long long zsw = pack2(zi[p - 1], zr[p - 1]);
            zP[p] = fma2(bi2, zsw, mul2(ar2, zP[p - 1]));
            unpack2(zP[p], zr[p], zi[p]);
        });

        // nsi[q] = -zi[q]^2, only q <= 5 needed
        float nsi[6];
        static_for<0, 6>([&](auto qc) {
            constexpr int q = decltype(qc)::value;
            nsi[q] = zi[q] * (-zi[q]);    // operand-negate, one FMUL
        });

        // vq[q] = (-|z1|^2)^q, q = 0..4 (m>0 pairs have q <= 4)
        float vq[5];
        vq[0] = 1.0f;
        vq[1] = xy2 * -0.25f;        // FMUL-imm
        vq[2] = vq[1] * vq[1];
        vq[3] = vq[2] * vq[1];
        vq[4] = vq[2] * vq[2];

        // 36 (p,q) pairs, p >= q, k = p+q <= 10
        static_for<0, 11>([&](auto pc) {
            constexpr int p = decltype(pc)::value;
            static_for<0, p + 1>([&](auto qc) {
                constexpr int q = decltype(qc)::value;
                if constexpr (p + q <= 10) {
                    constexpr int k = p + q;
                    constexpr int m = p - q;
                    const float c = w[k] * cB(p, q);          // FMUL-imm, rt1
                    if constexpr (m == 0) {
                        const float D  = fmaf(zr[p], zr[p], nsi[p]);
                        const float Dc = D * c;
                        static_for<k, 11>([&](auto lc) {
                            constexpr int l = decltype(lc)::value;
                            acc0[l] = fmaf(Dc, h[l - k], acc0[l]);
                        });
                    } else {
                        // (D, P) in ONE packed FMA:
                        //   D = zr[p]^2 - zi[q]^2, P = vq[q]*zi[m]  (signed)
                        const unsigned long long DP =
                            fma2(pack2(zr[p], vq[q]),
                                 pack2(zr[p], zi[m]),
                                 pack2(nsi[q], 0.0f));
                        const unsigned long long DPc = mul2(DP, pack2(c, c));
                        static_for<k, 11>([&](auto lc) {
                            constexpr int l = decltype(lc)::value;
                            acc2[aidx(l, m)] = fma2(DPc, h2[l - k], acc2[aidx(l, m)]);
                        });
                    }
                }
            });
        });
    }

    // ---- block-level reduction: shfl within warp, smem across 8 warps ----
    __shared__ float sred[NTHR / 32][121];
    const int lane = threadIdx.x & 31;
    const int wid  = threadIdx.x >> 5;

    auto wreduce = [&](float v, int j) {
#pragma unroll
        for (int o = 16; o > 0; o >>= 1) v += __shfl_xor_sync(0xffffffffu, v, o);
        if (lane == 0) sred[wid][j] = v;
    };

    static_for<0, 11>([&](auto lc) {
        constexpr int l = decltype(lc)::value;
        wreduce(acc0[l], l * l + l);
        static_for<1, l + 1>([&](auto mc) {
            constexpr int m = decltype(mc)::value;
            float re, im;
            unpack2(acc2[aidx(l, m)], re, im);
            wreduce(re, l * l + l + m);
            wreduce(im, l * l + l - m);
        });
    });
    __syncthreads();

    if (threadIdx.x < 121) {
        float s = 0.0f;
#pragma unroll
        for (int wv = 0; wv < NTHR / 32; ++wv) s += sred[wv][threadIdx.x];
        g_part[threadIdx.x * NBLK + blockIdx.x] = s;
    }
}

// ---------------------------------------------------------------------------
// Wide-parallel reduce: one block per coefficient, one LDG.128 per thread.
__global__ __launch_bounds__(128, 1)
void sht_reduce_kernel(float* __restrict__ out) {
    const int j    = blockIdx.x;          // 0..120
    const int t    = threadIdx.x;         // 0..127
    const int lane = t & 31;
    const int wid  = t >> 5;

    float s = 0.0f;
    if (t < NBLK / 4) {                   // 76 threads
        const float4 v =
            reinterpret_cast<const float4*>(g_part + j * NBLK)[t];
        s = (v.x + v.y) + (v.z + v.w);
    }
#pragma unroll
    for (int o = 16; o > 0; o >>= 1) s += __shfl_xor_sync(0xffffffffu, s, o);

    __shared__ float sm[4];
    if (lane == 0) sm[wid] = s;
    __syncthreads();
    if (t == 0)
        out[j] = ((sm[0] + sm[1]) + (sm[2] + sm[3])) * SCALES.v[j];
}

// ---------------------------------------------------------------------------
// Empty parity kernel: shifts ncu's (-s 5 -c 1) capture slot onto the main
// kernel. Launch order per call = (dummy, main, dummy, reduce) -> launch #6
// is sht_main_kernel.
__global__ void sht_parity_dummy() {}

// ---------------------------------------------------------------------------
extern "C" void kernel_launch(void* const* d_in, const int* in_sizes, int n_in,
                              void* d_out, int out_size) {
    const float* pos = (const float*)d_in[0];
    const int npts = in_sizes[0] / 3;
    sht_parity_dummy<<<1, 32>>>();
    sht_main_kernel<<<NBLK, NTHR>>>(pos, npts);
    sht_parity_dummy<<<1, 32>>>();
    sht_reduce_kernel<<<121, 128>>>((float*)d_out);
}

// round 12
// speedup vs baseline: 1.0653x; 1.0653x over previous
#include <cuda_runtime.h>
#include <cuda_bf16.h>

// ---------------------------------------------------------------------------
// SphericalHarmonicTransform, L=10, N=2e6 points -> 121 coefficients.
// R12 = R10 loop body, occupancy bump: 384 threads/CTA (12 warps/SM,
// 3 warps/SMSP, +50% latency hiding), 152 blocks = one CTA per SM, one wave.
// ptxas reg target 170 (65536/384). Reduce kernel: float4, 38 loads.
// ---------------------------------------------------------------------------

#define NBLK 152
#define NTHR 384

__device__ float g_part[121 * NBLK];   // per-block partials, [j][block]

// ----- compile-time math -----
__host__ __device__ constexpr double cfact(int n) {
    double r = 1.0;
    for (int i = 2; i <= n; ++i) r *= (double)i;
    return r;
}
__host__ __device__ constexpr double csqrt(double x) {
    if (x <= 0.0) return 0.0;
    double g = (x > 1.0) ? x : 1.0;
    for (int i = 0; i < 200; ++i) g = 0.5 * (g + x / g);
    return g;
}
__host__ __device__ constexpr float cB(int p, int q) {
    return (float)(1.0 / (cfact(p) * cfact(q)));
}

// epilogue scales A(l,m), fully compile-time
struct ScaleTab { float v[121]; };
__host__ __device__ constexpr ScaleTab make_scales() {
    ScaleTab t{};
    for (int l = 0; l <= 10; ++l) {
        for (int M = -l; M <= l; ++M) {
            const int j  = l * l + l + M;
            const int am = (M < 0) ? -M : M;
            double s = csqrt(cfact(l + am)) * csqrt(cfact(l - am)) *
                       csqrt((2.0 * l + 1.0) /
                             (4.0 * 3.14159265358979323846264338327950288));
            if (am) s *= csqrt(2.0) * ((am & 1) ? -1.0 : 1.0);
            t.v[j] = (float)s;
        }
    }
    return t;
}
__device__ __constant__ ScaleTab SCALES = make_scales();

// ----- compile-time for -----
template <int N> struct IntC { static constexpr int value = N; };
template <int Start, int End, class F>
__device__ __forceinline__ void static_for(F&& f) {
    if constexpr (Start < End) {
        f(IntC<Start>{});
        static_for<Start + 1, End>(static_cast<F&&>(f));
    }
}

// ----- packed f32x2 helpers -----
__device__ __forceinline__ unsigned long long pack2(float lo, float hi) {
    unsigned long long r;
    asm("mov.b64 %0, {%1, %2};" : "=l"(r) : "f"(lo), "f"(hi));
    return r;
}
__device__ __forceinline__ void unpack2(unsigned long long v, float& lo, float& hi) {
    asm("mov.b64 {%0, %1}, %2;" : "=f"(lo), "=f"(hi) : "l"(v));
}
__device__ __forceinline__ unsigned long long fma2(unsigned long long a,
                                                   unsigned long long b,
                                                   unsigned long long c) {
    unsigned long long d;
    asm("fma.rn.f32x2 %0, %1, %2, %3;" : "=l"(d) : "l"(a), "l"(b), "l"(c));
    return d;
}
__device__ __forceinline__ unsigned long long mul2(unsigned long long a,
                                                   unsigned long long b) {
    unsigned long long d;
    asm("mul.rn.f32x2 %0, %1, %2;" : "=l"(d) : "l"(a), "l"(b));
    return d;
}

__host__ __device__ constexpr int aidx(int l, int m) { return l * (l - 1) / 2 + (m - 1); }

// ---------------------------------------------------------------------------
__global__ __launch_bounds__(NTHR, 1)
void sht_main_kernel(const float* __restrict__ pos, int npts) {
    unsigned long long acc2[55];   // (l,m>0): lo = +m (real), hi = -m (imag)
    float acc0[11];                // m == 0
#pragma unroll
    for (int j = 0; j < 55; ++j) acc2[j] = 0ull;
#pragma unroll
    for (int j = 0; j < 11; ++j) acc0[j] = 0.0f;

    const int stride = gridDim.x * blockDim.x;
    for (int i = blockIdx.x * blockDim.x + threadIdx.x; i < npts; i += stride) {
        const float x  = pos[3 * i + 0];
        const float y  = pos[3 * i + 1];
        const float z0 = pos[3 * i + 2];

        const float xy2 = fmaf(x, x, y * y);
        const float r2  = fmaf(z0, z0, xy2);
        const float r   = sqrtf(r2);

        // packed (w,h) chain: wh[k] = (mask*z0*r^k, r^k/k!)
        const float w0 = (r2 > 0.0f) ? z0 : 0.0f;
        unsigned long long wh[11];
        float w[11], h[11];
        unsigned long long h2[11];
        wh[0] = pack2(w0, 1.0f);
        w[0] = w0; h[0] = 1.0f;
        h2[0] = pack2(1.0f, 1.0f);
        static_for<1, 11>([&](auto sc) {
            constexpr int s = decltype(sc)::value;
            const float rs = r * (float)(1.0 / (double)s);   // FMUL-imm, rt1
            wh[s] = mul2(wh[s - 1], pack2(r, rs));           // one FMUL2
            unpack2(wh[s], w[s], h[s]);
            h2[s] = pack2(h[s], h[s]);
        });

        // packed z^p chain: z = (zr, zi), z1 = (-x/2, -y/2)
        const float ar = -0.5f * x;
        const float ai = -0.5f * y;
        const unsigned long long ar2 = pack2(ar, ar);
        const unsigned long long bi2 = pack2(-ai, ai);
        unsigned long long zP[11];
        float zr[11], zi[11];
        zP[0] = pack2(1.0f, 0.0f);
        zr[0] = 1.0f; zi[0] = 0.0f;
        static_for<1, 11>([&](auto pc) {
            constexpr int p = decltype(pc)::value;
            const unsigned long long zsw = pack2(zi[p - 1], zr[p - 1]);
            zP[p] = fma2(bi2, zsw, mul2(ar2, zP[p - 1]));
            unpack2(zP[p], zr[p], zi[p]);
        });

        // nsi[q] = -zi[q]^2, only q <= 5 needed
        float nsi[6];
        static_for<0, 6>([&](auto qc) {
            constexpr int q = decltype(qc)::value;
            nsi[q] = zi[q] * (-zi[q]);    // operand-negate, one FMUL
        });

        // vq[q] = (-|z1|^2)^q, q = 0..4 (m>0 pairs have q <= 4)
        float vq[5];
        vq[0] = 1.0f;
        vq[1] = xy2 * -0.25f;        // FMUL-imm
        vq[2] = vq[1] * vq[1];
        vq[3] = vq[2] * vq[1];
        vq[4] = vq[2] * vq[2];

        // 36 (p,q) pairs, p >= q, k = p+q <= 10
        static_for<0, 11>([&](auto pc) {
            constexpr int p = decltype(pc)::value;
            static_for<0, p + 1>([&](auto qc) {
                constexpr int q = decltype(qc)::value;
                if constexpr (p + q <= 10) {
                    constexpr int k = p + q;
                    constexpr int m = p - q;
                    const float c = w[k] * cB(p, q);          // FMUL-imm, rt1
                    if constexpr (m == 0) {
                        const float D  = fmaf(zr[p], zr[p], nsi[p]);
                        const float Dc = D * c;
                        static_for<k, 11>([&](auto lc) {
                            constexpr int l = decltype(lc)::value;
                            acc0[l] = fmaf(Dc, h[l - k], acc0[l]);
                        });
                    } else {
                        // (D, P) in ONE packed FMA:
                        //   D = zr[p]^2 - zi[q]^2, P = vq[q]*zi[m]  (signed)
                        const unsigned long long DP =
                            fma2(pack2(zr[p], vq[q]),
                                 pack2(zr[p], zi[m]),
                                 pack2(nsi[q], 0.0f));
                        const unsigned long long DPc = mul2(DP, pack2(c, c));
                        static_for<k, 11>([&](auto lc) {
                            constexpr int l = decltype(lc)::value;
                            acc2[aidx(l, m)] = fma2(DPc, h2[l - k], acc2[aidx(l, m)]);
                        });
                    }
                }
            });
        });
    }

    // ---- block-level reduction: shfl within warp, smem across 12 warps ----
    __shared__ float sred[NTHR / 32][121];
    const int lane = threadIdx.x & 31;
    const int wid  = threadIdx.x >> 5;

    auto wreduce = [&](float v, int j) {
#pragma unroll
        for (int o = 16; o > 0; o >>= 1) v += __shfl_xor_sync(0xffffffffu, v, o);
        if (lane == 0) sred[wid][j] = v;
    };

    static_for<0, 11>([&](auto lc) {
        constexpr int l = decltype(lc)::value;
        wreduce(acc0[l], l * l + l);
        static_for<1, l + 1>([&](auto mc) {
            constexpr int m = decltype(mc)::value;
            float re, im;
            unpack2(acc2[aidx(l, m)], re, im);
            wreduce(re, l * l + l + m);
            wreduce(im, l * l + l - m);
        });
    });
    __syncthreads();

    if (threadIdx.x < 121) {
        float s = 0.0f;
#pragma unroll
        for (int wv = 0; wv < NTHR / 32; ++wv) s += sred[wv][threadIdx.x];
        g_part[threadIdx.x * NBLK + blockIdx.x] = s;
    }
}

// ---------------------------------------------------------------------------
// Wide-parallel reduce: one block per coefficient, one LDG.128 per thread.
// NBLK=152 -> 38 float4 loads cover all partials of one coefficient.
__global__ __launch_bounds__(128, 1)
void sht_reduce_kernel(float* __restrict__ out) {
    const int j    = blockIdx.x;          // 0..120
    const int t    = threadIdx.x;         // 0..127
    const int lane = t & 31;
    const int wid  = t >> 5;

    float s = 0.0f;
    if (t < NBLK / 4) {                   // 38 threads
        const float4 v =
            reinterpret_cast<const float4*>(g_part + j * NBLK)[t];
        s = (v.x + v.y) + (v.z + v.w);
    }
#pragma unroll
    for (int o = 16; o > 0; o >>= 1) s += __shfl_xor_sync(0xffffffffu, s, o);

    __shared__ float sm[4];
    if (lane == 0) sm[wid] = s;
    __syncthreads();
    if (t == 0)
        out[j] = ((sm[0] + sm[1]) + (sm[2] + sm[3])) * SCALES.v[j];
}

// ---------------------------------------------------------------------------
extern "C" void kernel_launch(void* const* d_in, const int* in_sizes, int n_in,
                              void* d_out, int out_size) {
    const float* pos = (const float*)d_in[0];
    const int npts = in_sizes[0] / 3;
    sht_main_kernel<<<NBLK, NTHR>>>(pos, npts);
    sht_reduce_kernel<<<121, 128>>>((float*)d_out);
}